// round 1
// baseline (speedup 1.0000x reference)
#include <cuda_runtime.h>
#include <math.h>

// Problem constants
#define BATCH 16
#define NATOM 20
#define NEDGE 380            // 20*19
#define TSEQ  63             // T-1
#define HD    256            // hidden
#define G     1024           // 4*HD
#define NROWS (BATCH*NATOM)  // 320 motion rows
#define EROWS (BATCH*NEDGE)  // 6080 edge rows

// ---------------- device scratch (static, no allocations) ----------------
__device__ float g_hm[NROWS*TSEQ*HD];     // motion hidden sequence [row][t][256]
__device__ float g_Qs[NROWS*TSEQ*G];      // hm @ (We_top@Wei)
__device__ float g_Qr[NROWS*TSEQ*G];      // hm @ (We_bot@Wei)
__device__ float g_hn[2][NROWS*HD];
__device__ float g_cn[2][NROWS*HD];
__device__ float g_he[2][EROWS*HD];
__device__ float g_ce[2][EROWS*HD];
__device__ float g_Wcomb[4*G];            // Wm @ Wmi
__device__ float g_bcomb[G];              // bm@Wmi + bmi
__device__ float g_WsP[HD*G];             // We[0:256]@Wei
__device__ float g_WrP[HD*G];             // We[256:512]@Wei
__device__ float g_cb[G];                 // be@Wei + bei
__device__ int   g_send[NEDGE], g_rec[NEDGE], g_einv[NATOM*NATOM];
__device__ float g_A[EROWS];

__device__ __forceinline__ float sigf(float x) { return 1.0f / (1.0f + expf(-x)); }

// ---------------- prep kernels ----------------
__global__ void prep_edges_k(const float* __restrict__ rel_rec,
                             const float* __restrict__ rel_send) {
    int e = blockIdx.x * blockDim.x + threadIdx.x;
    if (e >= NEDGE) return;
    int s = 0, r = 0;
    for (int n = 0; n < NATOM; n++) {
        if (rel_send[e*NATOM + n] > 0.5f) s = n;
        if (rel_rec [e*NATOM + n] > 0.5f) r = n;
    }
    g_send[e] = s; g_rec[e] = r;
    g_einv[s*NATOM + r] = e;
}

__global__ void prep_small_k(const float* __restrict__ Wm, const float* __restrict__ bm,
                             const float* __restrict__ Wmi, const float* __restrict__ bmi,
                             const float* __restrict__ be, const float* __restrict__ Wei,
                             const float* __restrict__ bei) {
    int g = blockIdx.x * blockDim.x + threadIdx.x;
    if (g >= G) return;
    for (int d = 0; d < 4; d++) {
        float s = 0.f;
        for (int k = 0; k < 128; k++) s += Wm[d*128 + k] * Wmi[k*G + g];
        g_Wcomb[d*G + g] = s;
    }
    float sb = 0.f, sc = 0.f;
    for (int k = 0; k < 128; k++) {
        sb += bm[k] * Wmi[k*G + g];
        sc += be[k] * Wei[k*G + g];
    }
    g_bcomb[g] = sb + bmi[g];
    g_cb[g]    = sc + bei[g];
}

__global__ void prep_wsp_k(const float* __restrict__ We, const float* __restrict__ Wei) {
    int o = blockIdx.x * blockDim.x + threadIdx.x;
    if (o >= 2*HD*G) return;
    int which = o >> 18;          // 0 -> sender half, 1 -> receiver half
    int a = (o >> 10) & 255;
    int g = o & 1023;
    const float* Wrow = We + (which*HD + a) * 128;
    float s = 0.f;
    for (int k = 0; k < 128; k++) s += Wrow[k] * Wei[k*G + g];
    if (which) g_WrP[a*G + g] = s; else g_WsP[a*G + g] = s;
}

__global__ void zero_state_k() {
    int i = blockIdx.x * blockDim.x + threadIdx.x;
    if (i < NROWS*HD) { g_hn[0][i] = 0.f; g_cn[0][i] = 0.f; }
    if (i < EROWS*HD) { g_he[0][i] = 0.f; g_ce[0][i] = 0.f; }
}

// ---------------- motion LSTM step ----------------
// block: 128 threads, j = blockIdx.x*128+tid in [0,256); RT rows per block.
template<int RT>
__global__ void motion_step_k(const float* __restrict__ X,   // [320][64][4]
                              const float* __restrict__ Wh,  // Wmh [256][1024]
                              const float* __restrict__ bh,  // bmh [1024]
                              int t, int par) {
    __shared__ float Hs[RT][HD];
    const float* h_in = g_hn[par];
    const float* c_in = g_cn[par];
    float* h_out = g_hn[par ^ 1];
    float* c_out = g_cn[par ^ 1];
    int j  = blockIdx.x * 128 + threadIdx.x;
    int r0 = blockIdx.y * RT;
    for (int idx = threadIdx.x; idx < RT*HD; idx += 128)
        Hs[idx / HD][idx % HD] = h_in[(r0 + idx / HD)*HD + (idx % HD)];
    __syncthreads();

    float a0[RT], a1[RT], a2[RT], a3[RT];
#pragma unroll
    for (int r = 0; r < RT; r++) { a0[r]=0.f; a1[r]=0.f; a2[r]=0.f; a3[r]=0.f; }

#pragma unroll 4
    for (int k = 0; k < HD; k++) {
        float w0 = Wh[k*G + j];
        float w1 = Wh[k*G + 256 + j];
        float w2 = Wh[k*G + 512 + j];
        float w3 = Wh[k*G + 768 + j];
#pragma unroll
        for (int r = 0; r < RT; r++) {
            float hv = Hs[r][k];
            a0[r] += w0*hv; a1[r] += w1*hv; a2[r] += w2*hv; a3[r] += w3*hv;
        }
    }

#pragma unroll
    for (int r = 0; r < RT; r++) {
        int row = r0 + r;
        const float* xp = X + row*64*4 + t*4;
        float d0 = xp[4]-xp[0], d1 = xp[5]-xp[1], d2 = xp[6]-xp[2], d3 = xp[7]-xp[3];
        float pre[4];
#pragma unroll
        for (int gq = 0; gq < 4; gq++) {
            int gc = gq*256 + j;
            pre[gq] = g_bcomb[gc] + bh[gc]
                    + d0*g_Wcomb[0*G+gc] + d1*g_Wcomb[1*G+gc]
                    + d2*g_Wcomb[2*G+gc] + d3*g_Wcomb[3*G+gc];
        }
        float iv = sigf(pre[0] + a0[r]);
        float fv = sigf(pre[1] + a1[r]);
        float gv = tanhf(pre[2] + a2[r]);
        float ov = sigf(pre[3] + a3[r]);
        float cv = fv * c_in[row*HD + j] + iv * gv;
        float hv = ov * tanhf(cv);
        c_out[row*HD + j] = cv;
        h_out[row*HD + j] = hv;
        g_hm[(row*TSEQ + t)*HD + j] = hv;
    }
}

// ---------------- GEMM: C[M][1024] = A[M][256] @ B[256][1024] ----------------
// mode 0: A=g_hm, B=g_WsP, C=g_Qs ; mode 1: A=g_hm, B=g_WrP, C=g_Qr
template<int RT>
__global__ void gemm_h_k(int mode) {
    __shared__ float As[RT][HD];
    const float* A = g_hm;
    const float* B = mode ? g_WrP : g_WsP;
    float*       C = mode ? g_Qr  : g_Qs;
    int j  = blockIdx.x * 128 + threadIdx.x;
    int r0 = blockIdx.y * RT;
    for (int idx = threadIdx.x; idx < RT*HD; idx += 128)
        As[idx / HD][idx % HD] = A[(r0 + idx / HD)*HD + (idx % HD)];
    __syncthreads();

    float a0[RT], a1[RT], a2[RT], a3[RT];
#pragma unroll
    for (int r = 0; r < RT; r++) { a0[r]=0.f; a1[r]=0.f; a2[r]=0.f; a3[r]=0.f; }

#pragma unroll 4
    for (int k = 0; k < HD; k++) {
        float w0 = B[k*G + j];
        float w1 = B[k*G + 256 + j];
        float w2 = B[k*G + 512 + j];
        float w3 = B[k*G + 768 + j];
#pragma unroll
        for (int r = 0; r < RT; r++) {
            float hv = As[r][k];
            a0[r] += w0*hv; a1[r] += w1*hv; a2[r] += w2*hv; a3[r] += w3*hv;
        }
    }
#pragma unroll
    for (int r = 0; r < RT; r++) {
        int row = r0 + r;
        C[row*G + j      ] = a0[r];
        C[row*G + 256 + j] = a1[r];
        C[row*G + 512 + j] = a2[r];
        C[row*G + 768 + j] = a3[r];
    }
}

// ---------------- edge LSTM step ----------------
template<int RT>
__global__ void edge_step_k(const float* __restrict__ Wh,  // Weh [256][1024]
                            const float* __restrict__ bh,  // beh [1024]
                            int t, int par) {
    __shared__ float Hs[RT][HD];
    const float* h_in = g_he[par];
    const float* c_in = g_ce[par];
    float* h_out = g_he[par ^ 1];
    float* c_out = g_ce[par ^ 1];
    int j  = blockIdx.x * 128 + threadIdx.x;
    int r0 = blockIdx.y * RT;
    for (int idx = threadIdx.x; idx < RT*HD; idx += 128)
        Hs[idx / HD][idx % HD] = h_in[(r0 + idx / HD)*HD + (idx % HD)];
    __syncthreads();

    float a0[RT], a1[RT], a2[RT], a3[RT];
#pragma unroll
    for (int r = 0; r < RT; r++) { a0[r]=0.f; a1[r]=0.f; a2[r]=0.f; a3[r]=0.f; }

#pragma unroll 4
    for (int k = 0; k < HD; k++) {
        float w0 = Wh[k*G + j];
        float w1 = Wh[k*G + 256 + j];
        float w2 = Wh[k*G + 512 + j];
        float w3 = Wh[k*G + 768 + j];
#pragma unroll
        for (int r = 0; r < RT; r++) {
            float hv = Hs[r][k];
            a0[r] += w0*hv; a1[r] += w1*hv; a2[r] += w2*hv; a3[r] += w3*hv;
        }
    }

#pragma unroll
    for (int r = 0; r < RT; r++) {
        int row = r0 + r;
        int b = row / NEDGE;
        int e = row - b*NEDGE;
        long srow = (long)((b*NATOM + g_send[e])*TSEQ + t) * G;
        long rrow = (long)((b*NATOM + g_rec [e])*TSEQ + t) * G;
        float pre[4];
#pragma unroll
        for (int gq = 0; gq < 4; gq++) {
            int gc = gq*256 + j;
            pre[gq] = g_Qs[srow + gc] + g_Qr[rrow + gc] + g_cb[gc] + bh[gc];
        }
        float iv = sigf(pre[0] + a0[r]);
        float fv = sigf(pre[1] + a1[r]);
        float gv = tanhf(pre[2] + a2[r]);
        float ov = sigf(pre[3] + a3[r]);
        float cv = fv * c_in[row*HD + j] + iv * gv;
        float hv = ov * tanhf(cv);
        c_out[row*HD + j] = cv;
        h_out[row*HD + j] = hv;
    }
}

// ---------------- finalization ----------------
__global__ void score_k(const float* __restrict__ Wf, const float* __restrict__ bf,
                        int final_par) {
    int row = blockIdx.x * blockDim.x + threadIdx.x;
    if (row >= EROWS) return;
    const float* h = g_he[final_par] + row*HD;
    float s = 0.f;
    for (int k = 0; k < HD; k++) s += h[k] * Wf[k];
    g_A[row] = sigf(s + bf[0]);
}

__global__ void assemble_k(float* __restrict__ out) {
    int i = blockIdx.x * blockDim.x + threadIdx.x;
    if (i >= BATCH*NATOM*NATOM) return;
    int b = i / (NATOM*NATOM);
    int nm = i % (NATOM*NATOM);
    int n = nm / NATOM, m = nm % NATOM;
    float v = 0.f;
    if (n != m) {
        int e1 = g_einv[n*NATOM + m];
        int e2 = g_einv[m*NATOM + n];
        v = 0.5f * (g_A[b*NEDGE + e1] + g_A[b*NEDGE + e2]);
    }
    out[i] = v;
}

// ---------------- launcher ----------------
extern "C" void kernel_launch(void* const* d_in, const int* in_sizes, int n_in,
                              void* d_out, int out_size) {
    const float* X        = (const float*)d_in[0];
    const float* rel_rec  = (const float*)d_in[1];
    const float* rel_send = (const float*)d_in[2];
    const float* Wm  = (const float*)d_in[3];
    const float* bm  = (const float*)d_in[4];
    const float* Wmi = (const float*)d_in[5];
    const float* bmi = (const float*)d_in[6];
    const float* Wmh = (const float*)d_in[7];
    const float* bmh = (const float*)d_in[8];
    const float* We  = (const float*)d_in[9];
    const float* be  = (const float*)d_in[10];
    const float* Wei = (const float*)d_in[11];
    const float* bei = (const float*)d_in[12];
    const float* Weh = (const float*)d_in[13];
    const float* beh = (const float*)d_in[14];
    const float* Wf  = (const float*)d_in[15];
    const float* bf  = (const float*)d_in[16];
    float* out = (float*)d_out;

    prep_edges_k<<<2, 256>>>(rel_rec, rel_send);
    prep_small_k<<<4, 256>>>(Wm, bm, Wmi, bmi, be, Wei, bei);
    prep_wsp_k<<<(2*HD*G + 255)/256, 256>>>(We, Wei);
    zero_state_k<<<(EROWS*HD + 255)/256, 256>>>();

    // motion LSTM: 320 rows, RT=4 -> grid (2, 80)
    for (int t = 0; t < TSEQ; t++)
        motion_step_k<4><<<dim3(2, NROWS/4), 128>>>(X, Wmh, bmh, t, t & 1);

    // Qs / Qr : [20160,256] @ [256,1024]
    gemm_h_k<16><<<dim3(2, (NROWS*TSEQ)/16), 128>>>(0);
    gemm_h_k<16><<<dim3(2, (NROWS*TSEQ)/16), 128>>>(1);

    // edge LSTM: 6080 rows, RT=16 -> grid (2, 380)
    for (int t = 0; t < TSEQ; t++)
        edge_step_k<16><<<dim3(2, EROWS/16), 128>>>(Weh, beh, t, t & 1);

    // final hidden is in parity (62 & 1) ^ 1 = 1
    score_k<<<(EROWS + 255)/256, 256>>>(Wf, bf, 1);
    assemble_k<<<(BATCH*NATOM*NATOM + 255)/256, 256>>>(out);
}

// round 4
// speedup vs baseline: 2.5406x; 2.5406x over previous
#include <cuda_runtime.h>
#include <cuda_bf16.h>
#include <cstdint>
#include <math.h>

// Problem constants
#define BATCH 16
#define NATOM 20
#define NEDGE 380            // 20*19
#define TSEQ  63             // T-1
#define HD    256            // hidden
#define G     1024           // 4*HD
#define NROWS (BATCH*NATOM)  // 320 motion rows
#define EROWS (BATCH*NEDGE)  // 6080 edge rows
#define EPAD  6144           // 48*128
#define HMROWS (NROWS*TSEQ)  // 20160
#define HMPAD  20224         // 158*128
#define MT_E 48
#define MT_G 158

// smem tile layout: A[128][256] bf16 and B[128][256] bf16, padded row stride
#define LDK_PAD 528                       // 512 + 16 bytes
#define SM_A 0
#define SM_B (128*LDK_PAD)
#define SMEM_SZ (2*128*LDK_PAD)           // 135168 bytes

// ---------------- device scratch ----------------
__device__ __nv_bfloat16 g_hmbf[HMPAD*HD];     // motion hidden bf16 [row*63+t][256]
__device__ float g_Qs[HMPAD*G];                // hm@WsP + bias, permuted cols
__device__ float g_Qr[HMPAD*G];                // hm@WrP, permuted cols
__device__ __nv_bfloat16 g_hbf[2][EPAD*HD];    // edge hidden bf16 ping-pong
__device__ float g_cE[EPAD*HD];                // edge cell fp32
__device__ float g_hn[2][NROWS*HD];            // motion h/c ping-pong (fp32)
__device__ float g_cn[2][NROWS*HD];
__device__ float g_Wcomb[4*G];                 // Wm@Wmi
__device__ float g_bcomb[G];                   // bm@Wmi + bmi
__device__ float g_qbias[G];                   // (be@Wei + bei + beh), permuted cols
__device__ __nv_bfloat16 g_WehI[1024*256];     // Weh^T, permuted rows, k-contig
__device__ __nv_bfloat16 g_WspI[2*1024*256];   // (We@Wei)^T halves, permuted, k-contig
__device__ int   g_send[NEDGE], g_rec[NEDGE], g_einv[NATOM*NATOM];
__device__ int   g_sB[EROWS], g_rB[EROWS];     // float-index base into Qs/Qr per edge row
__device__ float g_A[EROWS];

__device__ __forceinline__ float sigf(float x) { return 1.0f / (1.0f + expf(-x)); }
__device__ __forceinline__ float tanha(float x) {
    float y; asm("tanh.approx.f32 %0, %1;" : "=f"(y) : "f"(x)); return y;
}
__device__ __forceinline__ float siga(float x) { return fmaf(0.5f, tanha(0.5f*x), 0.5f); }

__device__ __forceinline__ uint32_t smem_u32(const void* p) {
    uint32_t a;
    asm("{ .reg .u64 t; cvta.to.shared.u64 t, %1; cvt.u32.u64 %0, t; }" : "=r"(a) : "l"(p));
    return a;
}

__device__ __forceinline__ void ldmx4(uint32_t& r0, uint32_t& r1, uint32_t& r2, uint32_t& r3,
                                      uint32_t addr) {
    asm volatile("ldmatrix.sync.aligned.m8n8.x4.shared.b16 {%0,%1,%2,%3}, [%4];"
                 : "=r"(r0), "=r"(r1), "=r"(r2), "=r"(r3) : "r"(addr));
}
__device__ __forceinline__ void mma16816(float* d, uint32_t a0, uint32_t a1, uint32_t a2,
                                         uint32_t a3, uint32_t b0, uint32_t b1) {
    asm volatile(
        "mma.sync.aligned.m16n8k16.row.col.f32.bf16.bf16.f32 "
        "{%0,%1,%2,%3},{%4,%5,%6,%7},{%8,%9},{%0,%1,%2,%3};"
        : "+f"(d[0]), "+f"(d[1]), "+f"(d[2]), "+f"(d[3])
        : "r"(a0), "r"(a1), "r"(a2), "r"(a3), "r"(b0), "r"(b1));
}

// Shared GEMM core: CTA computes acc[16 n8-tiles][4] = A(128x256) @ B^T(128x256),
// warp wid owns rows wid*16..wid*16+15, all 128 n-cols of the chunk.
__device__ __forceinline__ void gemm_core(char* smem, int tid, float acc[16][4]) {
    int lane = tid & 31, wid = tid >> 5;
#pragma unroll
    for (int i = 0; i < 16; i++)
#pragma unroll
        for (int q = 0; q < 4; q++) acc[i][q] = 0.f;
    uint32_t sbase = smem_u32(smem);
    uint32_t aadr = sbase + SM_A + (wid*16 + (lane & 15))*LDK_PAD + (lane >> 4)*16;
    uint32_t badr = sbase + SM_B + (lane & 15)*LDK_PAD + (lane >> 4)*16;
#pragma unroll 4
    for (int ks = 0; ks < 16; ks++) {
        uint32_t a0, a1, a2, a3;
        ldmx4(a0, a1, a2, a3, aadr + ks*32);
#pragma unroll
        for (int tp = 0; tp < 8; tp++) {
            uint32_t b0, b1, b2, b3;
            ldmx4(b0, b1, b2, b3, badr + tp*16*LDK_PAD + ks*32);
            mma16816(acc[2*tp],     a0, a1, a2, a3, b0, b2);
            mma16816(acc[2*tp + 1], a0, a1, a2, a3, b1, b3);
        }
    }
}

__device__ __forceinline__ void copy_tiles(char* smem, int tid,
                                           const uint4* __restrict__ As,
                                           const uint4* __restrict__ Bs) {
#pragma unroll
    for (int i = 0; i < 16; i++) {
        int idx = tid + i*256;
        int row = idx >> 5, c16 = idx & 31;
        *(uint4*)(smem + SM_A + row*LDK_PAD + c16*16) = As[idx];
        *(uint4*)(smem + SM_B + row*LDK_PAD + c16*16) = Bs[idx];
    }
    __syncthreads();
}

// ---------------- prep kernels ----------------
__global__ void prep_edges_k(const float* __restrict__ rel_rec,
                             const float* __restrict__ rel_send) {
    int e = blockIdx.x * blockDim.x + threadIdx.x;
    if (e >= NEDGE) return;
    int s = 0, r = 0;
    for (int n = 0; n < NATOM; n++) {
        if (rel_send[e*NATOM + n] > 0.5f) s = n;
        if (rel_rec [e*NATOM + n] > 0.5f) r = n;
    }
    g_send[e] = s; g_rec[e] = r;
    g_einv[s*NATOM + r] = e;
}

__global__ void prep_rowbase_k() {
    int grow = blockIdx.x * blockDim.x + threadIdx.x;
    if (grow >= EROWS) return;
    int b = grow / NEDGE, e = grow - b*NEDGE;
    g_sB[grow] = ((b*NATOM + g_send[e])*TSEQ)*G;
    g_rB[grow] = ((b*NATOM + g_rec [e])*TSEQ)*G;
}

__global__ void prep_small_k(const float* __restrict__ Wm, const float* __restrict__ bm,
                             const float* __restrict__ Wmi, const float* __restrict__ bmi,
                             const float* __restrict__ be, const float* __restrict__ Wei,
                             const float* __restrict__ bei, const float* __restrict__ beh) {
    int g = blockIdx.x * blockDim.x + threadIdx.x;
    if (g >= G) return;
    for (int d = 0; d < 4; d++) {
        float s = 0.f;
        for (int k = 0; k < 128; k++) s += Wm[d*128 + k] * Wmi[k*G + g];
        g_Wcomb[d*G + g] = s;
    }
    float sb = 0.f, sc = 0.f;
    for (int k = 0; k < 128; k++) {
        sb += bm[k] * Wmi[k*G + g];
        sc += be[k] * Wei[k*G + g];
    }
    g_bcomb[g] = sb + bmi[g];
    // permuted column: n = chunk*128 + gate*32 + j_local, chunk = j>>5
    int gate = g >> 8, j = g & 255;
    int cc = j >> 5, jl = j & 31;
    g_qbias[cc*128 + gate*32 + jl] = sc + bei[g] + beh[g];
}

// Weh^T -> permuted row-major bf16 image [n][k], n = c*128 + gate*32 + jl
__global__ void prep_wehI_k(const float* __restrict__ Weh) {
    int id = blockIdx.x * blockDim.x + threadIdx.x;
    if (id >= 1024*256) return;
    int n = id >> 8, k = id & 255;
    int cc = n >> 7, rem = n & 127, gate = rem >> 5, jl = rem & 31;
    int j = cc*32 + jl;
    g_WehI[n*256 + k] = __float2bfloat16(Weh[k*G + gate*256 + j]);
}

// (We@Wei)^T halves -> permuted bf16 image
__global__ void prep_wspI_k(const float* __restrict__ We, const float* __restrict__ Wei) {
    int id = blockIdx.x * blockDim.x + threadIdx.x;
    if (id >= 2*256*1024) return;
    int which = id >> 18;
    int k = (id >> 10) & 255;
    int n = id & 1023;
    int cc = n >> 7, rem = n & 127, gate = rem >> 5, jl = rem & 31;
    int gcol = gate*256 + cc*32 + jl;
    const float* Wrow = We + (which*HD + k) * 128;
    float s = 0.f;
    for (int d = 0; d < 128; d++) s += Wrow[d] * Wei[d*G + gcol];
    g_WspI[(which*1024 + n)*256 + k] = __float2bfloat16(s);
}

__global__ void zero_state_k() {
    int i = blockIdx.x * blockDim.x + threadIdx.x;
    if (i < EPAD*HD) {
        g_hbf[0][i] = __float2bfloat16(0.f);
        g_hbf[1][i] = __float2bfloat16(0.f);
        g_cE[i] = 0.f;
    }
    if (i < NROWS*HD) { g_hn[0][i] = 0.f; g_cn[0][i] = 0.f; }
    if (i < (HMPAD - HMROWS)*HD) g_hmbf[HMROWS*HD + i] = __float2bfloat16(0.f);
}

// ---------------- motion LSTM step (fp32 SIMT, exact) ----------------
template<int RT>
__global__ void motion_step_k(const float* __restrict__ X,
                              const float* __restrict__ Wh,
                              const float* __restrict__ bh,
                              int t, int par) {
    __shared__ float Hs[RT][HD];
    const float* h_in = g_hn[par];
    const float* c_in = g_cn[par];
    float* h_out = g_hn[par ^ 1];
    float* c_out = g_cn[par ^ 1];
    int j  = blockIdx.x * 128 + threadIdx.x;
    int r0 = blockIdx.y * RT;
    for (int idx = threadIdx.x; idx < RT*HD; idx += 128)
        Hs[idx / HD][idx % HD] = h_in[(r0 + idx / HD)*HD + (idx % HD)];
    __syncthreads();

    float a0[RT], a1[RT], a2[RT], a3[RT];
#pragma unroll
    for (int r = 0; r < RT; r++) { a0[r]=0.f; a1[r]=0.f; a2[r]=0.f; a3[r]=0.f; }
#pragma unroll 4
    for (int k = 0; k < HD; k++) {
        float w0 = Wh[k*G + j];
        float w1 = Wh[k*G + 256 + j];
        float w2 = Wh[k*G + 512 + j];
        float w3 = Wh[k*G + 768 + j];
#pragma unroll
        for (int r = 0; r < RT; r++) {
            float hv = Hs[r][k];
            a0[r] += w0*hv; a1[r] += w1*hv; a2[r] += w2*hv; a3[r] += w3*hv;
        }
    }
#pragma unroll
    for (int r = 0; r < RT; r++) {
        int row = r0 + r;
        const float* xp = X + row*64*4 + t*4;
        float d0 = xp[4]-xp[0], d1 = xp[5]-xp[1], d2 = xp[6]-xp[2], d3 = xp[7]-xp[3];
        float pre[4];
#pragma unroll
        for (int gq = 0; gq < 4; gq++) {
            int gc = gq*256 + j;
            pre[gq] = g_bcomb[gc] + bh[gc]
                    + d0*g_Wcomb[0*G+gc] + d1*g_Wcomb[1*G+gc]
                    + d2*g_Wcomb[2*G+gc] + d3*g_Wcomb[3*G+gc];
        }
        float iv = sigf(pre[0] + a0[r]);
        float fv = sigf(pre[1] + a1[r]);
        float gv = tanhf(pre[2] + a2[r]);
        float ov = sigf(pre[3] + a3[r]);
        float cv = fv * c_in[row*HD + j] + iv * gv;
        float hv = ov * tanhf(cv);
        c_out[row*HD + j] = cv;
        h_out[row*HD + j] = hv;
        g_hmbf[(row*TSEQ + t)*HD + j] = __float2bfloat16(hv);
    }
}

// ---------------- TC GEMM: Q{s,r} = hmbf @ WspI (+bias for mode 0) ----------------
__global__ void __launch_bounds__(256) gemm_tc_k(int mode) {
    extern __shared__ char smem[];
    int tid = threadIdx.x;
    int c = blockIdx.x, m = blockIdx.y;
    const uint4* As = (const uint4*)(g_hmbf + (size_t)m*128*HD);
    const uint4* Bs = (const uint4*)g_WspI + (size_t)mode*32768 + (size_t)c*4096;
    copy_tiles(smem, tid, As, Bs);

    float acc[16][4];
    gemm_core(smem, tid, acc);

    int lane = tid & 31, wid = tid >> 5;
    int row0 = m*128 + wid*16 + (lane >> 2);
    float* Qout = mode ? g_Qr : g_Qs;
#pragma unroll
    for (int rr = 0; rr < 2; rr++) {
        int grow = row0 + rr*8;
        if (grow >= HMROWS) continue;
        float* out = Qout + (size_t)grow*G + c*128;
#pragma unroll
        for (int tile = 0; tile < 16; tile++) {
            int c0 = tile*8 + 2*(lane & 3);
            float v0 = acc[tile][rr*2 + 0];
            float v1 = acc[tile][rr*2 + 1];
            if (mode == 0) {
                v0 += g_qbias[c*128 + c0];
                v1 += g_qbias[c*128 + c0 + 1];
            }
            *(float2*)(out + c0) = make_float2(v0, v1);
        }
    }
}

// ---------------- TC edge LSTM step ----------------
__global__ void __launch_bounds__(256) edge_tc_k(int t, int par) {
    extern __shared__ char smem[];
    int tid = threadIdx.x;
    int c = blockIdx.x, m = blockIdx.y;
    const uint4* As = (const uint4*)(g_hbf[par] + (size_t)m*128*HD);
    const uint4* Bs = (const uint4*)g_WehI + (size_t)c*4096;
    copy_tiles(smem, tid, As, Bs);

    float acc[16][4];
    gemm_core(smem, tid, acc);

    int lane = tid & 31, wid = tid >> 5;
    int row0 = m*128 + wid*16 + (lane >> 2);
    __nv_bfloat16* hOut = g_hbf[par ^ 1];
#pragma unroll
    for (int rr = 0; rr < 2; rr++) {
        int grow = row0 + rr*8;
        if (grow >= EROWS) continue;
        int qoff = t*G + c*128;
        const float* QsP = g_Qs + g_sB[grow] + qoff;
        const float* QrP = g_Qr + g_rB[grow] + qoff;
        float* cP = g_cE + (size_t)grow*HD + c*32;
        __nv_bfloat16* hP = hOut + (size_t)grow*HD + c*32;
#pragma unroll
        for (int tq = 0; tq < 4; tq++) {
#pragma unroll
            for (int d = 0; d < 2; d++) {
                int jl = tq*8 + 2*(lane & 3) + d;
                float pi = acc[0*4 + tq][rr*2 + d] + QsP[0*32 + jl] + QrP[0*32 + jl];
                float pf = acc[1*4 + tq][rr*2 + d] + QsP[1*32 + jl] + QrP[1*32 + jl];
                float pg = acc[2*4 + tq][rr*2 + d] + QsP[2*32 + jl] + QrP[2*32 + jl];
                float po = acc[3*4 + tq][rr*2 + d] + QsP[3*32 + jl] + QrP[3*32 + jl];
                float iv = siga(pi), fv = siga(pf), gv = tanha(pg), ov = siga(po);
                float cn = fmaf(fv, cP[jl], iv*gv);
                cP[jl] = cn;
                hP[jl] = __float2bfloat16(ov * tanha(cn));
            }
        }
    }
}

// ---------------- finalization ----------------
__global__ void score_k(const float* __restrict__ Wf, const float* __restrict__ bf) {
    int row = blockIdx.x * blockDim.x + threadIdx.x;
    if (row >= EROWS) return;
    const __nv_bfloat16* h = g_hbf[1] + (size_t)row*HD;
    float s = 0.f;
    for (int k = 0; k < HD; k++) s += __bfloat162float(h[k]) * Wf[k];
    g_A[row] = sigf(s + bf[0]);
}

__global__ void assemble_k(float* __restrict__ out) {
    int i = blockIdx.x * blockDim.x + threadIdx.x;
    if (i >= BATCH*NATOM*NATOM) return;
    int b = i / (NATOM*NATOM);
    int nm = i % (NATOM*NATOM);
    int n = nm / NATOM, mm = nm % NATOM;
    float v = 0.f;
    if (n != mm) {
        int e1 = g_einv[n*NATOM + mm];
        int e2 = g_einv[mm*NATOM + n];
        v = 0.5f * (g_A[b*NEDGE + e1] + g_A[b*NEDGE + e2]);
    }
    out[i] = v;
}

// ---------------- launcher ----------------
extern "C" void kernel_launch(void* const* d_in, const int* in_sizes, int n_in,
                              void* d_out, int out_size) {
    const float* X        = (const float*)d_in[0];
    const float* rel_rec  = (const float*)d_in[1];
    const float* rel_send = (const float*)d_in[2];
    const float* Wm  = (const float*)d_in[3];
    const float* bm  = (const float*)d_in[4];
    const float* Wmi = (const float*)d_in[5];
    const float* bmi = (const float*)d_in[6];
    const float* Wmh = (const float*)d_in[7];
    const float* bmh = (const float*)d_in[8];
    const float* We  = (const float*)d_in[9];
    const float* be  = (const float*)d_in[10];
    const float* Wei = (const float*)d_in[11];
    const float* bei = (const float*)d_in[12];
    const float* Weh = (const float*)d_in[13];
    const float* beh = (const float*)d_in[14];
    const float* Wf  = (const float*)d_in[15];
    const float* bf  = (const float*)d_in[16];
    float* out = (float*)d_out;

    static bool attr_done = false;
    if (!attr_done) {
        (void)cudaFuncSetAttribute(gemm_tc_k, cudaFuncAttributeMaxDynamicSharedMemorySize, SMEM_SZ);
        (void)cudaFuncSetAttribute(edge_tc_k, cudaFuncAttributeMaxDynamicSharedMemorySize, SMEM_SZ);
        attr_done = true;
    }

    prep_edges_k<<<2, 256>>>(rel_rec, rel_send);
    prep_rowbase_k<<<(EROWS + 255)/256, 256>>>();
    prep_small_k<<<4, 256>>>(Wm, bm, Wmi, bmi, be, Wei, bei, beh);
    prep_wehI_k<<<(1024*256 + 255)/256, 256>>>(Weh);
    prep_wspI_k<<<(2*256*1024 + 255)/256, 256>>>(We, Wei);
    zero_state_k<<<(EPAD*HD + 255)/256, 256>>>();

    for (int t = 0; t < TSEQ; t++)
        motion_step_k<4><<<dim3(2, NROWS/4), 128>>>(X, Wmh, bmh, t, t & 1);

    gemm_tc_k<<<dim3(8, MT_G), 256, SMEM_SZ>>>(0);
    gemm_tc_k<<<dim3(8, MT_G), 256, SMEM_SZ>>>(1);

    for (int t = 0; t < TSEQ; t++)
        edge_tc_k<<<dim3(8, MT_E), 256, SMEM_SZ>>>(t, t & 1);

    score_k<<<(EROWS + 255)/256, 256>>>(Wf, bf);
    assemble_k<<<(BATCH*NATOM*NATOM + 255)/256, 256>>>(out);
}